// round 2
// baseline (speedup 1.0000x reference)
#include <cuda_runtime.h>
#include <math_constants.h>

#define T_LEN 8192
#define B_SZ  256
#define E_CH  8
#define KS    15
#define TILE_A 2048
#define TD    1024
#define TPI_F 6.28318530717958647692f

__device__ __forceinline__ float2 cmulf(float2 a, float2 b) {
    return make_float2(a.x * b.x - a.y * b.y, a.x * b.y + a.y * b.x);
}

// ---------------------------------------------------------------------------
// Kernel A: fused per-channel dilated conv pair -> latent (B,E,T)
// grid: B*E*(T/TILE_A) blocks, 256 threads. h stored as float2 (2 channels).
// ---------------------------------------------------------------------------
__global__ __launch_bounds__(256) void latent_kernel(
    const float* __restrict__ x,
    const float* __restrict__ W1, const float* __restrict__ b1,
    const float* __restrict__ W2, const float* __restrict__ b2,
    float* __restrict__ latent)
{
    extern __shared__ float sm[];
    const int blk  = blockIdx.x;
    const int tile = blk & 3;           // T/TILE_A = 4
    const int be   = blk >> 2;
    const int e    = be & 7;
    const int b    = be >> 3;
    const int d    = 1 << e;            // dilation
    const int t0   = tile * TILE_A;

    float*  sx  = sm;                              // TILE_A + 28*128 floats
    float2* sh2 = (float2*)(sm + (TILE_A + 28 * 128));   // TILE_A + 14*128 float2
    const int XL = TILE_A + 28 * d;
    const int HL = TILE_A + 14 * d;
    const int xs = t0 - 14 * d;
    const int hs = t0 - 7 * d;

    const float* xrow = x + (size_t)b * T_LEN;
    for (int i = threadIdx.x; i < XL; i += blockDim.x) {
        int g = xs + i;
        sx[i] = (g >= 0 && g < T_LEN) ? xrow[g] : 0.f;
    }

    float w1a[KS], w1b[KS], w2a[KS], w2b[KS];
#pragma unroll
    for (int j = 0; j < KS; j++) {
        w1a[j] = W1[(e * 2 + 0) * KS + j];
        w1b[j] = W1[(e * 2 + 1) * KS + j];
        w2a[j] = W2[(e * 2 + 0) * KS + j];
        w2b[j] = W2[(e * 2 + 1) * KS + j];
    }
    const float bb1a = b1[e * 2], bb1b = b1[e * 2 + 1], bb2 = b2[e];
    __syncthreads();

    for (int i = threadIdx.x; i < HL; i += blockDim.x) {
        int g = hs + i;
        float h0 = 0.f, h1 = 0.f;
        if (g >= 0 && g < T_LEN) {
            h0 = bb1a; h1 = bb1b;
#pragma unroll
            for (int j = 0; j < KS; j++) {
                float xv = sx[i + j * d];
                h0 += w1a[j] * xv;
                h1 += w1b[j] * xv;
            }
        }
        sh2[i] = make_float2(h0, h1);
    }
    __syncthreads();

    float* lrow = latent + (size_t)be * T_LEN + t0;
    for (int i = threadIdx.x; i < TILE_A; i += blockDim.x) {
        float acc = bb2;
#pragma unroll
        for (int k = 0; k < KS; k++) {
            float2 hv = sh2[i + k * d];
            acc += w2a[k] * hv.x + w2b[k] * hv.y;
        }
        lrow[i] = acc;
    }
}

// ---------------------------------------------------------------------------
// Kernel B: per-(b,e) row — fc dots, real FFT (8192 real via complex 4096),
// radix-4 Stockham (6 stages, 1024 threads, 1 butterfly/thread),
// spectral reductions, scalar outputs p/f/a/b_off.
// ---------------------------------------------------------------------------
__global__ __launch_bounds__(1024) void fft_kernel(
    const float* __restrict__ latent,
    const float* __restrict__ fcW, const float* __restrict__ fcb,
    float* __restrict__ pOut, float* __restrict__ fOut,
    float* __restrict__ aOut, float* __restrict__ bOut)
{
    const int M = 4096;                 // complex FFT length
    extern __shared__ float smf[];
    float2* bufA = (float2*)smf;        // 4096
    float2* bufB = bufA + M;            // 4096
    float2* tw   = bufB + M;            // 1024 twiddles e^{-2pi i j/4096}
    __shared__ double red[128];

    const int be = blockIdx.x;
    const int e  = be & 7;
    const int tid = threadIdx.x;

    const float2* rowc = (const float2*)(latent + (size_t)be * T_LEN);
    const float2* fw0  = (const float2*)(fcW + (size_t)(e * 2 + 0) * T_LEN);
    const float2* fw1  = (const float2*)(fcW + (size_t)(e * 2 + 1) * T_LEN);

    double v0 = 0.0, v1 = 0.0;
#pragma unroll
    for (int i = tid; i < M; i += 1024) {
        float2 z = rowc[i];
        bufA[i] = z;
        float2 a0 = fw0[i], a1 = fw1[i];
        v0 += (double)(z.x * a0.x + z.y * a0.y);
        v1 += (double)(z.x * a1.x + z.y * a1.y);
    }
    {
        float s, c;
        sincosf(-(float)CUDART_PI * (float)tid / 2048.0f, &s, &c);
        tw[tid] = make_float2(c, s);
    }
    __syncthreads();

    // radix-4 Stockham autosort, 6 stages, M = 4^6
    float2* bin  = bufA;
    float2* bout = bufB;
#pragma unroll
    for (int sg = 0; sg < 6; sg++) {
        const int m = 1 << (2 * sg);
        const int idx = tid;                 // 1024 butterflies
        const int r = idx & (m - 1);
        float2 W  = tw[r << (10 - 2 * sg)];
        float2 z0 = bin[idx];
        float2 z1 = bin[idx + 1024];
        float2 z2 = bin[idx + 2048];
        float2 z3 = bin[idx + 3072];
        float2 W2 = make_float2(W.x * W.x - W.y * W.y, 2.f * W.x * W.y);
        float2 W3 = cmulf(W2, W);
        float2 t2 = cmulf(W2, z2);
        float2 g1 = cmulf(W, z1);
        float2 g3 = cmulf(W3, z3);
        float2 ev = make_float2(z0.x + t2.x, z0.y + t2.y);
        float2 fo = make_float2(z0.x - t2.x, z0.y - t2.y);
        float2 gg = make_float2(g1.x + g3.x, g1.y + g3.y);
        float2 hh = make_float2(g1.x - g3.x, g1.y - g3.y);
        const int ob = ((idx - r) << 2) + r;
        bout[ob]         = make_float2(ev.x + gg.x, ev.y + gg.y);
        bout[ob + m]     = make_float2(fo.x + hh.y, fo.y - hh.x);   // f - i h
        bout[ob + 2 * m] = make_float2(ev.x - gg.x, ev.y - gg.y);
        bout[ob + 3 * m] = make_float2(fo.x - hh.y, fo.y + hh.x);   // f + i h
        __syncthreads();
        float2* tmp = bin; bin = bout; bout = tmp;
    }
    // bin (= bufA) now holds Z_k in natural order

    double psum = 0.0, wsum = 0.0;
#pragma unroll
    for (int k0 = 0; k0 < 4; k0++) {
        int k = tid + 1 + k0 * 1024;
        if (k < M) {
            float2 zk = bin[k];
            float2 zm = bin[M - k];
            float Ax = 0.5f * (zk.x + zm.x), Ay = 0.5f * (zk.y - zm.y);
            float Bx = 0.5f * (zk.x - zm.x), By = 0.5f * (zk.y + zm.y);
            float s, c;
            __sincosf(-(float)CUDART_PI * (float)k / (float)M, &s, &c);
            float Xr = Ax + c * By + s * Bx;
            float Xi = Ay - c * Bx + s * By;
            float pw = Xr * Xr + Xi * Xi;
            psum += (double)pw;
            wsum += (double)k * (double)pw;
        }
    }
    if (tid == 0) {
        float xm = bin[0].x - bin[0].y;   // Nyquist bin (real)
        psum += (double)(xm * xm);
        wsum += (double)M * (double)(xm * xm);
    }

    const unsigned mask = 0xffffffffu;
#pragma unroll
    for (int o = 16; o > 0; o >>= 1) {
        psum += __shfl_down_sync(mask, psum, o);
        wsum += __shfl_down_sync(mask, wsum, o);
        v0   += __shfl_down_sync(mask, v0, o);
        v1   += __shfl_down_sync(mask, v1, o);
    }
    const int warp = tid >> 5, lane = tid & 31;
    if (lane == 0) {
        red[warp] = psum; red[32 + warp] = wsum;
        red[64 + warp] = v0; red[96 + warp] = v1;
    }
    __syncthreads();
    if (tid == 0) {
        double P = 0, Wm = 0, V0 = 0, V1 = 0;
        for (int i = 0; i < 32; i++) {
            P += red[i]; Wm += red[32 + i]; V0 += red[64 + i]; V1 += red[96 + i];
        }
        V0 += (double)fcb[e * 2];
        V1 += (double)fcb[e * 2 + 1];
        float f    = (float)(0.5 * Wm / P);
        float a    = 2.0f * sqrtf((float)P) / (float)T_LEN;
        float boff = (bin[0].x + bin[0].y) / (float)T_LEN;
        float p    = atan2f((float)V1, (float)V0) / TPI_F;
        pOut[be] = p; fOut[be] = f; aOut[be] = a; bOut[be] = boff;
    }
}

// ---------------------------------------------------------------------------
// Kernel D: sinusoid resynthesis (sig) + fused 3-level grouped deconv tree.
// channel pairs stored interleaved as float2 through all levels.
// grid: B*(T/TD) blocks, 256 threads
// ---------------------------------------------------------------------------
__global__ __launch_bounds__(256) void sig_tree_kernel(
    const float* __restrict__ pArr, const float* __restrict__ fArr,
    const float* __restrict__ aArr, const float* __restrict__ bArr,
    const float* __restrict__ dW0, const float* __restrict__ db0,
    const float* __restrict__ dW1, const float* __restrict__ db1,
    const float* __restrict__ dW2, const float* __restrict__ db2,
    float* __restrict__ sig, float* __restrict__ outp)
{
    extern __shared__ float smd[];
    const int SW  = TD + 42;   // sig row width (halo 21 each side)
    const int W0L = TD + 28;
    const int W1L = TD + 14;
    float2* ssig2 = (float2*)smd;                      // 4 pairs * SW
    float2* sy0_2 = ssig2 + 4 * SW;                    // 2 pairs * W0L
    float2* sy1_2 = sy0_2 + 2 * W0L;                   // W1L
    __shared__ float sca[8], scf[8], scp[8], scb[8];
    __shared__ float sdw0[8 * KS], sdw1[4 * KS], sdw2[2 * KS];
    __shared__ float sdb0[4], sdb1[2], sdb2[1];

    const int blk  = blockIdx.x;
    const int tile = blk & 7;          // T/TD = 8
    const int b    = blk >> 3;
    const int t0   = tile * TD;
    const int tid  = threadIdx.x;

    if (tid < 8) {
        sca[tid] = aArr[b * 8 + tid]; scf[tid] = fArr[b * 8 + tid];
        scp[tid] = pArr[b * 8 + tid]; scb[tid] = bArr[b * 8 + tid];
    }
    if (tid < 8 * KS) sdw0[tid] = dW0[tid];
    if (tid < 4 * KS) sdw1[tid] = dW1[tid];
    if (tid < 2 * KS) sdw2[tid] = dW2[tid];
    if (tid < 4) sdb0[tid] = db0[tid];
    if (tid < 2) sdb1[tid] = db1[tid];
    if (tid == 0) sdb2[0] = db2[0];
    __syncthreads();

    const float inv = 2.0f / (float)(T_LEN - 1);
    for (int i = tid; i < 4 * SW; i += blockDim.x) {
        int pr = i / SW, j = i - pr * SW;
        int t = t0 - 21 + j;
        float v0 = 0.f, v1 = 0.f;
        if (t >= 0 && t < T_LEN) {
            float arg = -1.0f + (float)t * inv;
            int e0 = 2 * pr, e1 = 2 * pr + 1;
            v0 = sca[e0] * sinpif(2.0f * (scf[e0] * arg + scp[e0])) + scb[e0];
            v1 = sca[e1] * sinpif(2.0f * (scf[e1] * arg + scp[e1])) + scb[e1];
            if (t >= t0 && t < t0 + TD) {
                sig[((size_t)b * 8 + e0) * T_LEN + t] = v0;
                sig[((size_t)b * 8 + e1) * T_LEN + t] = v1;
            }
        }
        ssig2[i] = make_float2(v0, v1);
    }
    __syncthreads();

    // level 0: 4 groups, each reads its channel pair (float2)
    for (int i = tid; i < 4 * W0L; i += blockDim.x) {
        int g = i / W0L, j = i - g * W0L;
        int t = t0 - 14 + j;
        float acc = 0.f;
        if (t >= 0 && t < T_LEN) {
            acc = sdb0[g];
            const float2* s = ssig2 + g * SW + j;
            const float* wa = sdw0 + (2 * g) * KS;
            const float* wb = sdw0 + (2 * g + 1) * KS;
#pragma unroll
            for (int k = 0; k < KS; k++) {
                float2 sv = s[k];
                acc += wa[k] * sv.x + wb[k] * sv.y;
            }
        }
        // store interleaved by pair: pair = g>>1, comp = g&1
        ((float*)(sy0_2 + (g >> 1) * W0L + j))[g & 1] = acc;
    }
    __syncthreads();

    // level 1: 2 groups
    for (int i = tid; i < 2 * W1L; i += blockDim.x) {
        int g = i / W1L, j = i - g * W1L;
        int t = t0 - 7 + j;
        float acc = 0.f;
        if (t >= 0 && t < T_LEN) {
            acc = sdb1[g];
            const float2* s = sy0_2 + g * W0L + j;
            const float* wa = sdw1 + (2 * g) * KS;
            const float* wb = sdw1 + (2 * g + 1) * KS;
#pragma unroll
            for (int k = 0; k < KS; k++) {
                float2 sv = s[k];
                acc += wa[k] * sv.x + wb[k] * sv.y;
            }
        }
        ((float*)(sy1_2 + j))[g] = acc;
    }
    __syncthreads();

    // level 2: final
    for (int j = tid; j < TD; j += blockDim.x) {
        float acc = sdb2[0];
        const float2* s = sy1_2 + j;
#pragma unroll
        for (int k = 0; k < KS; k++) {
            float2 sv = s[k];
            acc += sdw2[k] * sv.x + sdw2[KS + k] * sv.y;
        }
        outp[(size_t)b * T_LEN + t0 + j] = acc;
    }
}

// ---------------------------------------------------------------------------
extern "C" void kernel_launch(void* const* d_in, const int* in_sizes, int n_in,
                              void* d_out, int out_size)
{
    const float* x   = (const float*)d_in[0];
    const float* W1  = (const float*)d_in[1];
    const float* b1  = (const float*)d_in[2];
    const float* W2  = (const float*)d_in[3];
    const float* b2  = (const float*)d_in[4];
    const float* fcW = (const float*)d_in[5];
    const float* fcb = (const float*)d_in[6];
    const float* dW0 = (const float*)d_in[7];
    const float* db0 = (const float*)d_in[8];
    const float* dW1 = (const float*)d_in[9];
    const float* db1 = (const float*)d_in[10];
    const float* dW2 = (const float*)d_in[11];
    const float* db2 = (const float*)d_in[12];

    float* out = (float*)d_out;
    float* outMain = out;                                        // (B, T)
    float* latent  = out + (size_t)B_SZ * T_LEN;                 // (B, E, T)
    float* sig     = latent + (size_t)B_SZ * E_CH * T_LEN;       // (B, E, T)
    float* pOut    = sig + (size_t)B_SZ * E_CH * T_LEN;          // (B, E, 1)
    float* fOut    = pOut + B_SZ * E_CH;
    float* aOut    = fOut + B_SZ * E_CH;
    float* bOut    = aOut + B_SZ * E_CH;

    const size_t smA = (size_t)(TILE_A + 28 * 128) * sizeof(float)
                     + (size_t)(TILE_A + 14 * 128) * sizeof(float2);
    const size_t smB = (size_t)(4096 + 4096 + 1024) * sizeof(float2);
    const size_t smD = (size_t)(4 * (TD + 42) + 2 * (TD + 28) + (TD + 14)) * sizeof(float2);

    cudaFuncSetAttribute(latent_kernel,   cudaFuncAttributeMaxDynamicSharedMemorySize, (int)smA);
    cudaFuncSetAttribute(fft_kernel,      cudaFuncAttributeMaxDynamicSharedMemorySize, (int)smB);
    cudaFuncSetAttribute(sig_tree_kernel, cudaFuncAttributeMaxDynamicSharedMemorySize, (int)smD);

    latent_kernel<<<B_SZ * E_CH * (T_LEN / TILE_A), 256, smA>>>(x, W1, b1, W2, b2, latent);
    fft_kernel<<<B_SZ * E_CH, 1024, smB>>>(latent, fcW, fcb, pOut, fOut, aOut, bOut);
    sig_tree_kernel<<<B_SZ * (T_LEN / TD), 256, smD>>>(pOut, fOut, aOut, bOut,
                                                       dW0, db0, dW1, db1, dW2, db2,
                                                       sig, outMain);
}

// round 3
// speedup vs baseline: 1.4066x; 1.4066x over previous
#include <cuda_runtime.h>
#include <math_constants.h>

#define T_LEN 8192
#define B_SZ  256
#define E_CH  8
#define KS    15
#define TD    1024
#define TPI_F 6.28318530717958647692f

#define PAD(i) ((i) + ((i) >> 5))

__device__ __forceinline__ float2 cmulf(float2 a, float2 b) {
    return make_float2(a.x * b.x - a.y * b.y, a.x * b.y + a.y * b.x);
}

// compensated float-float accumulation (TwoSum based)
__device__ __forceinline__ float2 df_add(float2 a, float2 b) {
    float s = a.x + b.x;
    float v = s - a.x;
    float e = (a.x - (s - v)) + (b.x - v);
    e = e + a.y + b.y;
    float hi = s + e;
    return make_float2(hi, e - (hi - s));
}
__device__ __forceinline__ float2 df_addf(float2 a, float b) {
    return df_add(a, make_float2(b, 0.f));
}

// ---------------------------------------------------------------------------
// Kernel A: fused per-channel dilated conv pair -> latent (B,E,T)
// One block per (b,e) row. Coset-blocked register streaming: each thread
// computes 8 outputs spaced d apart, sharing 14/15 taps in registers.
// smem arrays padded (1 float per 32) to kill strided bank conflicts.
// ---------------------------------------------------------------------------
__global__ __launch_bounds__(256, 2) void latent_kernel(
    const float* __restrict__ x,
    const float* __restrict__ W1, const float* __restrict__ b1,
    const float* __restrict__ W2, const float* __restrict__ b2,
    float* __restrict__ latent)
{
    extern __shared__ float sm[];
    float* sx  = sm;            // PAD(8192) = 8448
    float* sh0 = sm + 8448;
    float* sh1 = sm + 16896;

    const int be = blockIdx.x;
    const int e  = be & 7;
    const int b  = be >> 3;
    const int d  = 1 << e;
    const int tid = threadIdx.x;

    const float* xrow = x + (size_t)b * T_LEN;
    for (int i = tid; i < T_LEN; i += 256) sx[PAD(i)] = xrow[i];

    float w1a[KS], w1b[KS];
#pragma unroll
    for (int j = 0; j < KS; j++) {
        w1a[j] = W1[e * 30 + j];
        w1b[j] = W1[e * 30 + 15 + j];
    }
    const float bb1a = b1[2 * e], bb1b = b1[2 * e + 1];
    __syncthreads();

    // ---- stage 1: h (2 channels), only t in [0,T) (zeros implied outside)
#pragma unroll 1
    for (int it = 0; it < 4; it++) {
        const int cc = it * 256 + tid;
        const int p  = cc & (d - 1);
        const int qc = cc >> e;
        const int tb = p + (qc << (e + 3));     // p + qc*8*d
        float xv[22];
#pragma unroll
        for (int m = 0; m < 22; m++) {
            int idx = tb + (m - 7) * d;
            xv[m] = ((unsigned)idx < (unsigned)T_LEN) ? sx[PAD(idx)] : 0.f;
        }
#pragma unroll
        for (int rr = 0; rr < 8; rr++) {
            float h0 = bb1a, h1 = bb1b;
#pragma unroll
            for (int j = 0; j < KS; j++) {
                float v = xv[rr + j];
                h0 += w1a[j] * v;
                h1 += w1b[j] * v;
            }
            int t = tb + rr * d;
            sh0[PAD(t)] = h0;
            sh1[PAD(t)] = h1;
        }
    }

    float w2a[KS], w2b[KS];
#pragma unroll
    for (int k = 0; k < KS; k++) {
        w2a[k] = W2[e * 30 + k];
        w2b[k] = W2[e * 30 + 15 + k];
    }
    const float bb2 = b2[e];
    __syncthreads();

    // ---- stage 2: latent, results staged into sx (dead) for coalesced store
#pragma unroll 1
    for (int it = 0; it < 4; it++) {
        const int cc = it * 256 + tid;
        const int p  = cc & (d - 1);
        const int qc = cc >> e;
        const int tb = p + (qc << (e + 3));
        float g0[22], g1[22];
#pragma unroll
        for (int m = 0; m < 22; m++) {
            int idx = tb + (m - 7) * d;
            bool ok = ((unsigned)idx < (unsigned)T_LEN);
            g0[m] = ok ? sh0[PAD(idx)] : 0.f;
            g1[m] = ok ? sh1[PAD(idx)] : 0.f;
        }
#pragma unroll
        for (int rr = 0; rr < 8; rr++) {
            float acc = bb2;
#pragma unroll
            for (int k = 0; k < KS; k++) {
                acc += w2a[k] * g0[rr + k] + w2b[k] * g1[rr + k];
            }
            sx[PAD(tb + rr * d)] = acc;
        }
    }
    __syncthreads();

    float* lrow = latent + (size_t)be * T_LEN;
    for (int i = tid; i < T_LEN; i += 256) lrow[i] = sx[PAD(i)];
}

// ---------------------------------------------------------------------------
// Kernel B: per-(b,e) row — fc dots, real FFT (8192 real via complex 4096),
// radix-4 Stockham (6 stages, 1024 threads), compensated fp32 reductions.
// ---------------------------------------------------------------------------
__global__ __launch_bounds__(1024) void fft_kernel(
    const float* __restrict__ latent,
    const float* __restrict__ fcW, const float* __restrict__ fcb,
    float* __restrict__ pOut, float* __restrict__ fOut,
    float* __restrict__ aOut, float* __restrict__ bOut)
{
    const int M = 4096;
    extern __shared__ float smf[];
    float2* bufA = (float2*)smf;
    float2* bufB = bufA + M;
    float2* tw   = bufB + M;            // 1024 twiddles
    __shared__ float2 red2[128];

    const int be = blockIdx.x;
    const int e  = be & 7;
    const int tid = threadIdx.x;

    const float2* rowc = (const float2*)(latent + (size_t)be * T_LEN);
    const float2* fw0  = (const float2*)(fcW + (size_t)(e * 2 + 0) * T_LEN);
    const float2* fw1  = (const float2*)(fcW + (size_t)(e * 2 + 1) * T_LEN);

    float2 v0 = make_float2(0.f, 0.f), v1 = make_float2(0.f, 0.f);
#pragma unroll
    for (int i = tid; i < M; i += 1024) {
        float2 z = rowc[i];
        bufA[i] = z;
        float2 a0 = fw0[i], a1 = fw1[i];
        v0 = df_addf(v0, z.x * a0.x + z.y * a0.y);
        v1 = df_addf(v1, z.x * a1.x + z.y * a1.y);
    }
    {
        float s, c;
        sincosf(-(float)CUDART_PI * (float)tid / 2048.0f, &s, &c);
        tw[tid] = make_float2(c, s);
    }
    __syncthreads();

    // radix-4 Stockham autosort, 6 stages, M = 4^6
    float2* bin  = bufA;
    float2* bout = bufB;
#pragma unroll
    for (int sg = 0; sg < 6; sg++) {
        const int m = 1 << (2 * sg);
        const int idx = tid;
        const int r = idx & (m - 1);
        float2 W  = tw[r << (10 - 2 * sg)];
        float2 z0 = bin[idx];
        float2 z1 = bin[idx + 1024];
        float2 z2 = bin[idx + 2048];
        float2 z3 = bin[idx + 3072];
        float2 W2 = make_float2(W.x * W.x - W.y * W.y, 2.f * W.x * W.y);
        float2 W3 = cmulf(W2, W);
        float2 t2 = cmulf(W2, z2);
        float2 g1 = cmulf(W, z1);
        float2 g3 = cmulf(W3, z3);
        float2 ev = make_float2(z0.x + t2.x, z0.y + t2.y);
        float2 fo = make_float2(z0.x - t2.x, z0.y - t2.y);
        float2 gg = make_float2(g1.x + g3.x, g1.y + g3.y);
        float2 hh = make_float2(g1.x - g3.x, g1.y - g3.y);
        const int ob = ((idx - r) << 2) + r;
        bout[ob]         = make_float2(ev.x + gg.x, ev.y + gg.y);
        bout[ob + m]     = make_float2(fo.x + hh.y, fo.y - hh.x);
        bout[ob + 2 * m] = make_float2(ev.x - gg.x, ev.y - gg.y);
        bout[ob + 3 * m] = make_float2(fo.x - hh.y, fo.y + hh.x);
        __syncthreads();
        float2* tmp = bin; bin = bout; bout = tmp;
    }

    float2 psum = make_float2(0.f, 0.f), wsum = make_float2(0.f, 0.f);
#pragma unroll
    for (int k0 = 0; k0 < 4; k0++) {
        int k = tid + 1 + k0 * 1024;
        if (k < M) {
            float2 zk = bin[k];
            float2 zm = bin[M - k];
            float Ax = 0.5f * (zk.x + zm.x), Ay = 0.5f * (zk.y - zm.y);
            float Bx = 0.5f * (zk.x - zm.x), By = 0.5f * (zk.y + zm.y);
            float s, c;
            __sincosf(-(float)CUDART_PI * (float)k / (float)M, &s, &c);
            float Xr = Ax + c * By + s * Bx;
            float Xi = Ay - c * Bx + s * By;
            float pw = Xr * Xr + Xi * Xi;
            psum = df_addf(psum, pw);
            wsum = df_addf(wsum, (float)k * pw);
        }
    }
    if (tid == 0) {
        float xm = bin[0].x - bin[0].y;   // Nyquist bin (real)
        psum = df_addf(psum, xm * xm);
        wsum = df_addf(wsum, (float)M * (xm * xm));
    }

    const unsigned mask = 0xffffffffu;
#pragma unroll
    for (int o = 16; o > 0; o >>= 1) {
        psum = df_add(psum, make_float2(__shfl_down_sync(mask, psum.x, o),
                                        __shfl_down_sync(mask, psum.y, o)));
        wsum = df_add(wsum, make_float2(__shfl_down_sync(mask, wsum.x, o),
                                        __shfl_down_sync(mask, wsum.y, o)));
        v0   = df_add(v0,   make_float2(__shfl_down_sync(mask, v0.x, o),
                                        __shfl_down_sync(mask, v0.y, o)));
        v1   = df_add(v1,   make_float2(__shfl_down_sync(mask, v1.x, o),
                                        __shfl_down_sync(mask, v1.y, o)));
    }
    const int warp = tid >> 5, lane = tid & 31;
    if (lane == 0) {
        red2[warp] = psum; red2[32 + warp] = wsum;
        red2[64 + warp] = v0; red2[96 + warp] = v1;
    }
    __syncthreads();
    if (tid == 0) {
        double P = 0, Wm = 0, V0 = 0, V1 = 0;
        for (int i = 0; i < 32; i++) {
            P  += (double)red2[i].x      + (double)red2[i].y;
            Wm += (double)red2[32 + i].x + (double)red2[32 + i].y;
            V0 += (double)red2[64 + i].x + (double)red2[64 + i].y;
            V1 += (double)red2[96 + i].x + (double)red2[96 + i].y;
        }
        V0 += (double)fcb[e * 2];
        V1 += (double)fcb[e * 2 + 1];
        float f    = (float)(0.5 * Wm / P);
        float a    = 2.0f * sqrtf((float)P) / (float)T_LEN;
        float boff = (bin[0].x + bin[0].y) / (float)T_LEN;
        float p    = atan2f((float)V1, (float)V0) / TPI_F;
        pOut[be] = p; fOut[be] = f; aOut[be] = a; bOut[be] = boff;
    }
}

// ---------------------------------------------------------------------------
// Kernel D: sinusoid resynthesis via rotation recurrence + fused 3-level
// grouped deconv tree. Channel pairs interleaved as float2.
// ---------------------------------------------------------------------------
__global__ __launch_bounds__(256) void sig_tree_kernel(
    const float* __restrict__ pArr, const float* __restrict__ fArr,
    const float* __restrict__ aArr, const float* __restrict__ bArr,
    const float* __restrict__ dW0, const float* __restrict__ db0,
    const float* __restrict__ dW1, const float* __restrict__ db1,
    const float* __restrict__ dW2, const float* __restrict__ db2,
    float* __restrict__ sig, float* __restrict__ outp)
{
    extern __shared__ float smd[];
    const int SW  = TD + 42;
    const int W0L = TD + 28;
    const int W1L = TD + 14;
    float2* ssig2 = (float2*)smd;                      // 4 pairs * SW
    float2* sy0_2 = ssig2 + 4 * SW;                    // 2 pairs * W0L
    float2* sy1_2 = sy0_2 + 2 * W0L;                   // W1L
    __shared__ float sca[8], scf[8], scp[8], scb[8];
    __shared__ float2 rotv[8];
    __shared__ float sdw0[8 * KS], sdw1[4 * KS], sdw2[2 * KS];
    __shared__ float sdb0[4], sdb1[2], sdb2[1];

    const int blk  = blockIdx.x;
    const int tile = blk & 7;
    const int b    = blk >> 3;
    const int t0   = tile * TD;
    const int tid  = threadIdx.x;
    const float inv = 2.0f / (float)(T_LEN - 1);

    if (tid < 8) {
        float fv = fArr[b * 8 + tid];
        sca[tid] = aArr[b * 8 + tid]; scf[tid] = fv;
        scp[tid] = pArr[b * 8 + tid]; scb[tid] = bArr[b * 8 + tid];
        float S, C;
        sincospif(2.0f * fv * inv, &S, &C);
        rotv[tid] = make_float2(C, S);
    }
    if (tid < 8 * KS) sdw0[tid] = dW0[tid];
    if (tid < 4 * KS) sdw1[tid] = dW1[tid];
    if (tid < 2 * KS) sdw2[tid] = dW2[tid];
    if (tid < 4) sdb0[tid] = db0[tid];
    if (tid < 2) sdb1[tid] = db1[tid];
    if (tid == 0) sdb2[0] = db2[0];
    __syncthreads();

    // sinusoid generation: 64 threads per pair-row, 17 contiguous elems each
    {
        const int pr  = tid >> 6;
        const int sub = tid & 63;
        const int j0  = sub * 17;
        const int ts  = t0 - 21 + j0;
        const int e0 = 2 * pr, e1 = 2 * pr + 1;
        const float arg0 = -1.0f + (float)ts * inv;
        float s0, c0, s1, c1;
        sincospif(2.0f * (scf[e0] * arg0 + scp[e0]), &s0, &c0);
        sincospif(2.0f * (scf[e1] * arg0 + scp[e1]), &s1, &c1);
        const float2 r0 = rotv[e0], r1 = rotv[e1];
        const float a0 = sca[e0], b0 = scb[e0];
        const float a1 = sca[e1], b1v = scb[e1];
#pragma unroll
        for (int jj = 0; jj < 17; jj++) {
            int j = j0 + jj;
            int t = ts + jj;
            if (j < SW) {
                bool ok = ((unsigned)t < (unsigned)T_LEN);
                float v0 = ok ? (a0 * s0 + b0)  : 0.f;
                float v1 = ok ? (a1 * s1 + b1v) : 0.f;
                ssig2[pr * SW + j] = make_float2(v0, v1);
            }
            float ns0 = s0 * r0.x + c0 * r0.y;
            c0 = c0 * r0.x - s0 * r0.y; s0 = ns0;
            float ns1 = s1 * r1.x + c1 * r1.y;
            c1 = c1 * r1.x - s1 * r1.y; s1 = ns1;
        }
    }
    __syncthreads();

    // coalesced sig writeback
    for (int i = tid; i < 8 * TD; i += 256) {
        int e = i >> 10, jj = i & (TD - 1);
        float2 v = ssig2[(e >> 1) * SW + 21 + jj];
        sig[((size_t)b * 8 + e) * T_LEN + t0 + jj] = (e & 1) ? v.y : v.x;
    }

    // level 0: 4 groups
    for (int i = tid; i < 4 * W0L; i += 256) {
        int g = i / W0L, j = i - g * W0L;
        int t = t0 - 14 + j;
        float acc = 0.f;
        if (t >= 0 && t < T_LEN) {
            acc = sdb0[g];
            const float2* s = ssig2 + g * SW + j;
            const float* wa = sdw0 + (2 * g) * KS;
            const float* wb = sdw0 + (2 * g + 1) * KS;
#pragma unroll
            for (int k = 0; k < KS; k++) {
                float2 sv = s[k];
                acc += wa[k] * sv.x + wb[k] * sv.y;
            }
        }
        ((float*)(sy0_2 + (g >> 1) * W0L + j))[g & 1] = acc;
    }
    __syncthreads();

    // level 1: 2 groups
    for (int i = tid; i < 2 * W1L; i += 256) {
        int g = i / W1L, j = i - g * W1L;
        int t = t0 - 7 + j;
        float acc = 0.f;
        if (t >= 0 && t < T_LEN) {
            acc = sdb1[g];
            const float2* s = sy0_2 + g * W0L + j;
            const float* wa = sdw1 + (2 * g) * KS;
            const float* wb = sdw1 + (2 * g + 1) * KS;
#pragma unroll
            for (int k = 0; k < KS; k++) {
                float2 sv = s[k];
                acc += wa[k] * sv.x + wb[k] * sv.y;
            }
        }
        ((float*)(sy1_2 + j))[g] = acc;
    }
    __syncthreads();

    // level 2
    for (int j = tid; j < TD; j += 256) {
        float acc = sdb2[0];
        const float2* s = sy1_2 + j;
#pragma unroll
        for (int k = 0; k < KS; k++) {
            float2 sv = s[k];
            acc += sdw2[k] * sv.x + sdw2[KS + k] * sv.y;
        }
        outp[(size_t)b * T_LEN + t0 + j] = acc;
    }
}

// ---------------------------------------------------------------------------
extern "C" void kernel_launch(void* const* d_in, const int* in_sizes, int n_in,
                              void* d_out, int out_size)
{
    const float* x   = (const float*)d_in[0];
    const float* W1  = (const float*)d_in[1];
    const float* b1  = (const float*)d_in[2];
    const float* W2  = (const float*)d_in[3];
    const float* b2  = (const float*)d_in[4];
    const float* fcW = (const float*)d_in[5];
    const float* fcb = (const float*)d_in[6];
    const float* dW0 = (const float*)d_in[7];
    const float* db0 = (const float*)d_in[8];
    const float* dW1 = (const float*)d_in[9];
    const float* db1 = (const float*)d_in[10];
    const float* dW2 = (const float*)d_in[11];
    const float* db2 = (const float*)d_in[12];

    float* out = (float*)d_out;
    float* outMain = out;                                        // (B, T)
    float* latent  = out + (size_t)B_SZ * T_LEN;                 // (B, E, T)
    float* sig     = latent + (size_t)B_SZ * E_CH * T_LEN;       // (B, E, T)
    float* pOut    = sig + (size_t)B_SZ * E_CH * T_LEN;          // (B, E, 1)
    float* fOut    = pOut + B_SZ * E_CH;
    float* aOut    = fOut + B_SZ * E_CH;
    float* bOut    = aOut + B_SZ * E_CH;

    const size_t smA = (size_t)(3 * 8448) * sizeof(float);               // ~99KB
    const size_t smB = (size_t)(4096 + 4096 + 1024) * sizeof(float2);    // 72KB
    const size_t smD = (size_t)(4 * (TD + 42) + 2 * (TD + 28) + (TD + 14)) * sizeof(float2);

    cudaFuncSetAttribute(latent_kernel,   cudaFuncAttributeMaxDynamicSharedMemorySize, (int)smA);
    cudaFuncSetAttribute(fft_kernel,      cudaFuncAttributeMaxDynamicSharedMemorySize, (int)smB);
    cudaFuncSetAttribute(sig_tree_kernel, cudaFuncAttributeMaxDynamicSharedMemorySize, (int)smD);

    latent_kernel<<<B_SZ * E_CH, 256, smA>>>(x, W1, b1, W2, b2, latent);
    fft_kernel<<<B_SZ * E_CH, 1024, smB>>>(latent, fcW, fcb, pOut, fOut, aOut, bOut);
    sig_tree_kernel<<<B_SZ * (T_LEN / TD), 256, smD>>>(pOut, fOut, aOut, bOut,
                                                       dW0, db0, dW1, db1, dW2, db2,
                                                       sig, outMain);
}

// round 4
// speedup vs baseline: 1.7683x; 1.2571x over previous
#include <cuda_runtime.h>
#include <math_constants.h>

#define T_LEN 8192
#define B_SZ  256
#define E_CH  8
#define KS    15
#define TD    1024
#define TPI_F 6.28318530717958647692f

#define PAD(i)   ((i) + ((i) >> 5))
#define F2PAD(i) ((i) + ((i) >> 4))

__device__ __forceinline__ float2 cmulf(float2 a, float2 b) {
    return make_float2(a.x * b.x - a.y * b.y, a.x * b.y + a.y * b.x);
}
__device__ __forceinline__ float2 cadd(float2 a, float2 b) {
    return make_float2(a.x + b.x, a.y + b.y);
}
__device__ __forceinline__ float2 csub(float2 a, float2 b) {
    return make_float2(a.x - b.x, a.y - b.y);
}

// compensated float-float accumulation (TwoSum based)
__device__ __forceinline__ float2 df_add(float2 a, float2 b) {
    float s = a.x + b.x;
    float v = s - a.x;
    float e = (a.x - (s - v)) + (b.x - v);
    e = e + a.y + b.y;
    float hi = s + e;
    return make_float2(hi, e - (hi - s));
}
__device__ __forceinline__ float2 df_addf(float2 a, float b) {
    return df_add(a, make_float2(b, 0.f));
}

// ---------------------------------------------------------------------------
// Kernel A: fused per-channel dilated conv pair -> latent (B,E,T)
// One block per (b,e) row. Coset-blocked register streaming.
// ---------------------------------------------------------------------------
__global__ __launch_bounds__(256, 2) void latent_kernel(
    const float* __restrict__ x,
    const float* __restrict__ W1, const float* __restrict__ b1,
    const float* __restrict__ W2, const float* __restrict__ b2,
    float* __restrict__ latent)
{
    extern __shared__ float sm[];
    float* sx  = sm;            // PAD(8192) = 8448
    float* sh0 = sm + 8448;
    float* sh1 = sm + 16896;

    const int be = blockIdx.x;
    const int e  = be & 7;
    const int b  = be >> 3;
    const int d  = 1 << e;
    const int tid = threadIdx.x;

    const float* xrow = x + (size_t)b * T_LEN;
    for (int i = tid; i < T_LEN; i += 256) sx[PAD(i)] = xrow[i];

    float w1a[KS], w1b[KS];
#pragma unroll
    for (int j = 0; j < KS; j++) {
        w1a[j] = W1[e * 30 + j];
        w1b[j] = W1[e * 30 + 15 + j];
    }
    const float bb1a = b1[2 * e], bb1b = b1[2 * e + 1];
    __syncthreads();

#pragma unroll 1
    for (int it = 0; it < 4; it++) {
        const int cc = it * 256 + tid;
        const int p  = cc & (d - 1);
        const int qc = cc >> e;
        const int tb = p + (qc << (e + 3));
        float xv[22];
#pragma unroll
        for (int m = 0; m < 22; m++) {
            int idx = tb + (m - 7) * d;
            xv[m] = ((unsigned)idx < (unsigned)T_LEN) ? sx[PAD(idx)] : 0.f;
        }
#pragma unroll
        for (int rr = 0; rr < 8; rr++) {
            float h0 = bb1a, h1 = bb1b;
#pragma unroll
            for (int j = 0; j < KS; j++) {
                float v = xv[rr + j];
                h0 += w1a[j] * v;
                h1 += w1b[j] * v;
            }
            int t = tb + rr * d;
            sh0[PAD(t)] = h0;
            sh1[PAD(t)] = h1;
        }
    }

    float w2a[KS], w2b[KS];
#pragma unroll
    for (int k = 0; k < KS; k++) {
        w2a[k] = W2[e * 30 + k];
        w2b[k] = W2[e * 30 + 15 + k];
    }
    const float bb2 = b2[e];
    __syncthreads();

#pragma unroll 1
    for (int it = 0; it < 4; it++) {
        const int cc = it * 256 + tid;
        const int p  = cc & (d - 1);
        const int qc = cc >> e;
        const int tb = p + (qc << (e + 3));
        float g0[22], g1[22];
#pragma unroll
        for (int m = 0; m < 22; m++) {
            int idx = tb + (m - 7) * d;
            bool ok = ((unsigned)idx < (unsigned)T_LEN);
            g0[m] = ok ? sh0[PAD(idx)] : 0.f;
            g1[m] = ok ? sh1[PAD(idx)] : 0.f;
        }
#pragma unroll
        for (int rr = 0; rr < 8; rr++) {
            float acc = bb2;
#pragma unroll
            for (int k = 0; k < KS; k++) {
                acc += w2a[k] * g0[rr + k] + w2b[k] * g1[rr + k];
            }
            sx[PAD(tb + rr * d)] = acc;
        }
    }
    __syncthreads();

    float* lrow = latent + (size_t)be * T_LEN;
    for (int i = tid; i < T_LEN; i += 256) lrow[i] = sx[PAD(i)];
}

// ---------------------------------------------------------------------------
// Kernel B: per-(b,e) row — fc dots, real FFT (8192 real via complex 4096),
// radix-8 Stockham (4 stages, 512 threads, 1 DFT8/thread), padded smem,
// compensated fp32 reductions.
// ---------------------------------------------------------------------------
__global__ __launch_bounds__(512, 2) void fft_kernel(
    const float* __restrict__ latent,
    const float* __restrict__ fcW, const float* __restrict__ fcb,
    float* __restrict__ pOut, float* __restrict__ fOut,
    float* __restrict__ aOut, float* __restrict__ bOut)
{
    const int M = 4096;
    extern __shared__ float smf[];
    float2* bufA = (float2*)smf;         // F2PAD -> 4352 slots
    float2* bufB = bufA + 4352;
    float2* tw   = bufB + 4352;          // 512 twiddles e^{-2pi i j/4096}
    __shared__ float2 red2[64];

    const int be = blockIdx.x;
    const int e  = be & 7;
    const int tid = threadIdx.x;

    const float2* rowc = (const float2*)(latent + (size_t)be * T_LEN);
    const float2* fw0  = (const float2*)(fcW + (size_t)(e * 2 + 0) * T_LEN);
    const float2* fw1  = (const float2*)(fcW + (size_t)(e * 2 + 1) * T_LEN);

    float2 v0 = make_float2(0.f, 0.f), v1 = make_float2(0.f, 0.f);
#pragma unroll
    for (int i = tid; i < M; i += 512) {
        float2 z = rowc[i];
        bufA[F2PAD(i)] = z;
        float2 a0 = fw0[i], a1 = fw1[i];
        v0 = df_addf(v0, z.x * a0.x + z.y * a0.y);
        v1 = df_addf(v1, z.x * a1.x + z.y * a1.y);
    }
    {
        float s, c;
        sincosf(-(float)CUDART_PI * (float)tid / 2048.0f, &s, &c);
        tw[tid] = make_float2(c, s);
    }
    __syncthreads();

    // radix-8 Stockham autosort, 4 stages, M = 8^4
    const float RS = 0.70710678118654752440f;
    float2* bin  = bufA;
    float2* bout = bufB;
#pragma unroll
    for (int sg = 0; sg < 4; sg++) {
        const int m = 1 << (3 * sg);
        const int idx = tid;
        const int r = idx & (m - 1);
        float2 W = tw[r << (9 - 3 * sg)];

        float2 u0 = bin[F2PAD(idx)];
        float2 z1 = bin[F2PAD(idx + 512)];
        float2 z2 = bin[F2PAD(idx + 1024)];
        float2 z3 = bin[F2PAD(idx + 1536)];
        float2 z4 = bin[F2PAD(idx + 2048)];
        float2 z5 = bin[F2PAD(idx + 2560)];
        float2 z6 = bin[F2PAD(idx + 3072)];
        float2 z7 = bin[F2PAD(idx + 3584)];

        float2 Wc = W;
        float2 u1 = cmulf(z1, Wc); Wc = cmulf(Wc, W);
        float2 u2 = cmulf(z2, Wc); Wc = cmulf(Wc, W);
        float2 u3 = cmulf(z3, Wc); Wc = cmulf(Wc, W);
        float2 u4 = cmulf(z4, Wc); Wc = cmulf(Wc, W);
        float2 u5 = cmulf(z5, Wc); Wc = cmulf(Wc, W);
        float2 u6 = cmulf(z6, Wc); Wc = cmulf(Wc, W);
        float2 u7 = cmulf(z7, Wc);

        // even DFT4 (u0,u2,u4,u6)
        float2 t0 = cadd(u0, u4), t1 = csub(u0, u4);
        float2 t2 = cadd(u2, u6), t3 = csub(u2, u6);
        float2 E0 = cadd(t0, t2);
        float2 E1 = make_float2(t1.x + t3.y, t1.y - t3.x);   // t1 - i t3
        float2 E2 = csub(t0, t2);
        float2 E3 = make_float2(t1.x - t3.y, t1.y + t3.x);   // t1 + i t3
        // odd DFT4 (u1,u3,u5,u7)
        float2 s0 = cadd(u1, u5), s1 = csub(u1, u5);
        float2 s2 = cadd(u3, u7), s3 = csub(u3, u7);
        float2 O0 = cadd(s0, s2);
        float2 O1 = make_float2(s1.x + s3.y, s1.y - s3.x);
        float2 O2 = csub(s0, s2);
        float2 O3 = make_float2(s1.x - s3.y, s1.y + s3.x);
        // apply omega^q, omega = e^{-i pi/4}
        float2 Q1 = make_float2(RS * (O1.x + O1.y), RS * (O1.y - O1.x));
        float2 Q2 = make_float2(O2.y, -O2.x);
        float2 Q3 = make_float2(RS * (O3.y - O3.x), -RS * (O3.x + O3.y));

        const int ob = ((idx - r) << 3) + r;
        bout[F2PAD(ob)]         = cadd(E0, O0);
        bout[F2PAD(ob + m)]     = cadd(E1, Q1);
        bout[F2PAD(ob + 2 * m)] = cadd(E2, Q2);
        bout[F2PAD(ob + 3 * m)] = cadd(E3, Q3);
        bout[F2PAD(ob + 4 * m)] = csub(E0, O0);
        bout[F2PAD(ob + 5 * m)] = csub(E1, Q1);
        bout[F2PAD(ob + 6 * m)] = csub(E2, Q2);
        bout[F2PAD(ob + 7 * m)] = csub(E3, Q3);
        __syncthreads();
        float2* tmp = bin; bin = bout; bout = tmp;
    }
    // bin (= bufA) holds Z_k in natural order (padded)

    float2 psum = make_float2(0.f, 0.f), wsum = make_float2(0.f, 0.f);
#pragma unroll
    for (int k0 = 0; k0 < 8; k0++) {
        int k = tid + 1 + k0 * 512;
        if (k < M) {
            float2 zk = bin[F2PAD(k)];
            float2 zm = bin[F2PAD(M - k)];
            float Ax = 0.5f * (zk.x + zm.x), Ay = 0.5f * (zk.y - zm.y);
            float Bx = 0.5f * (zk.x - zm.x), By = 0.5f * (zk.y + zm.y);
            float s, c;
            __sincosf(-(float)CUDART_PI * (float)k / (float)M, &s, &c);
            float Xr = Ax + c * By + s * Bx;
            float Xi = Ay - c * Bx + s * By;
            float pw = Xr * Xr + Xi * Xi;
            psum = df_addf(psum, pw);
            wsum = df_addf(wsum, (float)k * pw);
        }
    }
    if (tid == 0) {
        float xm = bin[0].x - bin[0].y;   // Nyquist bin (real)
        psum = df_addf(psum, xm * xm);
        wsum = df_addf(wsum, (float)M * (xm * xm));
    }

    const unsigned mask = 0xffffffffu;
#pragma unroll
    for (int o = 16; o > 0; o >>= 1) {
        psum = df_add(psum, make_float2(__shfl_down_sync(mask, psum.x, o),
                                        __shfl_down_sync(mask, psum.y, o)));
        wsum = df_add(wsum, make_float2(__shfl_down_sync(mask, wsum.x, o),
                                        __shfl_down_sync(mask, wsum.y, o)));
        v0   = df_add(v0,   make_float2(__shfl_down_sync(mask, v0.x, o),
                                        __shfl_down_sync(mask, v0.y, o)));
        v1   = df_add(v1,   make_float2(__shfl_down_sync(mask, v1.x, o),
                                        __shfl_down_sync(mask, v1.y, o)));
    }
    const int warp = tid >> 5, lane = tid & 31;
    if (lane == 0) {
        red2[warp] = psum; red2[16 + warp] = wsum;
        red2[32 + warp] = v0; red2[48 + warp] = v1;
    }
    __syncthreads();
    if (tid == 0) {
        double P = 0, Wm = 0, V0 = 0, V1 = 0;
        for (int i = 0; i < 16; i++) {
            P  += (double)red2[i].x      + (double)red2[i].y;
            Wm += (double)red2[16 + i].x + (double)red2[16 + i].y;
            V0 += (double)red2[32 + i].x + (double)red2[32 + i].y;
            V1 += (double)red2[48 + i].x + (double)red2[48 + i].y;
        }
        V0 += (double)fcb[e * 2];
        V1 += (double)fcb[e * 2 + 1];
        float f    = (float)(0.5 * Wm / P);
        float a    = 2.0f * sqrtf((float)P) / (float)T_LEN;
        float boff = (bin[0].x + bin[0].y) / (float)T_LEN;
        float p    = atan2f((float)V1, (float)V0) / TPI_F;
        pOut[be] = p; fOut[be] = f; aOut[be] = a; bOut[be] = boff;
    }
}

// ---------------------------------------------------------------------------
// Kernel D: sinusoid resynthesis via rotation recurrence + fused 3-level
// grouped deconv tree. Channel pairs interleaved as float2. No int divs.
// ---------------------------------------------------------------------------
__global__ __launch_bounds__(256) void sig_tree_kernel(
    const float* __restrict__ pArr, const float* __restrict__ fArr,
    const float* __restrict__ aArr, const float* __restrict__ bArr,
    const float* __restrict__ dW0, const float* __restrict__ db0,
    const float* __restrict__ dW1, const float* __restrict__ db1,
    const float* __restrict__ dW2, const float* __restrict__ db2,
    float* __restrict__ sig, float* __restrict__ outp)
{
    extern __shared__ float smd[];
    const int SW  = TD + 42;
    const int W0L = TD + 28;
    const int W1L = TD + 14;
    float2* ssig2 = (float2*)smd;
    float2* sy0_2 = ssig2 + 4 * SW;
    float2* sy1_2 = sy0_2 + 2 * W0L;
    __shared__ float sca[8], scf[8], scp[8], scb[8];
    __shared__ float2 rotv[8];
    __shared__ float sdw0[8 * KS], sdw1[4 * KS], sdw2[2 * KS];
    __shared__ float sdb0[4], sdb1[2], sdb2[1];

    const int blk  = blockIdx.x;
    const int tile = blk & 7;
    const int b    = blk >> 3;
    const int t0   = tile * TD;
    const int tid  = threadIdx.x;
    const float inv = 2.0f / (float)(T_LEN - 1);

    if (tid < 8) {
        float fv = fArr[b * 8 + tid];
        sca[tid] = aArr[b * 8 + tid]; scf[tid] = fv;
        scp[tid] = pArr[b * 8 + tid]; scb[tid] = bArr[b * 8 + tid];
        float S, C;
        sincospif(2.0f * fv * inv, &S, &C);
        rotv[tid] = make_float2(C, S);
    }
    if (tid < 8 * KS) sdw0[tid] = dW0[tid];
    if (tid < 4 * KS) sdw1[tid] = dW1[tid];
    if (tid < 2 * KS) sdw2[tid] = dW2[tid];
    if (tid < 4) sdb0[tid] = db0[tid];
    if (tid < 2) sdb1[tid] = db1[tid];
    if (tid == 0) sdb2[0] = db2[0];
    __syncthreads();

    // sinusoid generation: 64 threads per pair-row, 17 contiguous elems each
    {
        const int pr  = tid >> 6;
        const int sub = tid & 63;
        const int j0  = sub * 17;
        const int ts  = t0 - 21 + j0;
        const int e0 = 2 * pr, e1 = 2 * pr + 1;
        const float arg0 = -1.0f + (float)ts * inv;
        float s0, c0, s1, c1;
        sincospif(2.0f * (scf[e0] * arg0 + scp[e0]), &s0, &c0);
        sincospif(2.0f * (scf[e1] * arg0 + scp[e1]), &s1, &c1);
        const float2 r0 = rotv[e0], r1 = rotv[e1];
        const float a0 = sca[e0], b0 = scb[e0];
        const float a1 = sca[e1], b1v = scb[e1];
#pragma unroll
        for (int jj = 0; jj < 17; jj++) {
            int j = j0 + jj;
            int t = ts + jj;
            if (j < SW) {
                bool ok = ((unsigned)t < (unsigned)T_LEN);
                float v0 = ok ? (a0 * s0 + b0)  : 0.f;
                float v1 = ok ? (a1 * s1 + b1v) : 0.f;
                ssig2[pr * SW + j] = make_float2(v0, v1);
            }
            float ns0 = s0 * r0.x + c0 * r0.y;
            c0 = c0 * r0.x - s0 * r0.y; s0 = ns0;
            float ns1 = s1 * r1.x + c1 * r1.y;
            c1 = c1 * r1.x - s1 * r1.y; s1 = ns1;
        }
    }
    __syncthreads();

    // coalesced sig writeback
    for (int i = tid; i < 8 * TD; i += 256) {
        int e = i >> 10, jj = i & (TD - 1);
        float2 v = ssig2[(e >> 1) * SW + 21 + jj];
        sig[((size_t)b * 8 + e) * T_LEN + t0 + jj] = (e & 1) ? v.y : v.x;
    }

    // level 0: 4 groups (group-outer loops: no integer division)
#pragma unroll 1
    for (int g = 0; g < 4; g++) {
        const float2* srow = ssig2 + g * SW;
        const float* wa = sdw0 + (2 * g) * KS;
        const float* wb = sdw0 + (2 * g + 1) * KS;
        const float bg = sdb0[g];
        float* dst = (float*)(sy0_2 + (g >> 1) * W0L);
        const int comp = g & 1;
        for (int j = tid; j < W0L; j += 256) {
            int t = t0 - 14 + j;
            float acc = 0.f;
            if ((unsigned)t < (unsigned)T_LEN) {
                acc = bg;
                const float2* s = srow + j;
#pragma unroll
                for (int k = 0; k < KS; k++) {
                    float2 sv = s[k];
                    acc += wa[k] * sv.x + wb[k] * sv.y;
                }
            }
            dst[2 * j + comp] = acc;
        }
    }
    __syncthreads();

    // level 1: 2 groups
#pragma unroll 1
    for (int g = 0; g < 2; g++) {
        const float2* srow = sy0_2 + g * W0L;
        const float* wa = sdw1 + (2 * g) * KS;
        const float* wb = sdw1 + (2 * g + 1) * KS;
        const float bg = sdb1[g];
        float* dst = (float*)sy1_2;
        for (int j = tid; j < W1L; j += 256) {
            int t = t0 - 7 + j;
            float acc = 0.f;
            if ((unsigned)t < (unsigned)T_LEN) {
                acc = bg;
                const float2* s = srow + j;
#pragma unroll
                for (int k = 0; k < KS; k++) {
                    float2 sv = s[k];
                    acc += wa[k] * sv.x + wb[k] * sv.y;
                }
            }
            dst[2 * j + g] = acc;
        }
    }
    __syncthreads();

    // level 2
    for (int j = tid; j < TD; j += 256) {
        float acc = sdb2[0];
        const float2* s = sy1_2 + j;
#pragma unroll
        for (int k = 0; k < KS; k++) {
            float2 sv = s[k];
            acc += sdw2[k] * sv.x + sdw2[KS + k] * sv.y;
        }
        outp[(size_t)b * T_LEN + t0 + j] = acc;
    }
}

// ---------------------------------------------------------------------------
extern "C" void kernel_launch(void* const* d_in, const int* in_sizes, int n_in,
                              void* d_out, int out_size)
{
    const float* x   = (const float*)d_in[0];
    const float* W1  = (const float*)d_in[1];
    const float* b1  = (const float*)d_in[2];
    const float* W2  = (const float*)d_in[3];
    const float* b2  = (const float*)d_in[4];
    const float* fcW = (const float*)d_in[5];
    const float* fcb = (const float*)d_in[6];
    const float* dW0 = (const float*)d_in[7];
    const float* db0 = (const float*)d_in[8];
    const float* dW1 = (const float*)d_in[9];
    const float* db1 = (const float*)d_in[10];
    const float* dW2 = (const float*)d_in[11];
    const float* db2 = (const float*)d_in[12];

    float* out = (float*)d_out;
    float* outMain = out;                                        // (B, T)
    float* latent  = out + (size_t)B_SZ * T_LEN;                 // (B, E, T)
    float* sig     = latent + (size_t)B_SZ * E_CH * T_LEN;       // (B, E, T)
    float* pOut    = sig + (size_t)B_SZ * E_CH * T_LEN;          // (B, E, 1)
    float* fOut    = pOut + B_SZ * E_CH;
    float* aOut    = fOut + B_SZ * E_CH;
    float* bOut    = aOut + B_SZ * E_CH;

    const size_t smA = (size_t)(3 * 8448) * sizeof(float);              // ~99KB
    const size_t smB = (size_t)(4352 * 2 + 512) * sizeof(float2);       // 73728B
    const size_t smD = (size_t)(4 * (TD + 42) + 2 * (TD + 28) + (TD + 14)) * sizeof(float2);

    cudaFuncSetAttribute(latent_kernel,   cudaFuncAttributeMaxDynamicSharedMemorySize, (int)smA);
    cudaFuncSetAttribute(fft_kernel,      cudaFuncAttributeMaxDynamicSharedMemorySize, (int)smB);
    cudaFuncSetAttribute(sig_tree_kernel, cudaFuncAttributeMaxDynamicSharedMemorySize, (int)smD);

    latent_kernel<<<B_SZ * E_CH, 256, smA>>>(x, W1, b1, W2, b2, latent);
    fft_kernel<<<B_SZ * E_CH, 512, smB>>>(latent, fcW, fcb, pOut, fOut, aOut, bOut);
    sig_tree_kernel<<<B_SZ * (T_LEN / TD), 256, smD>>>(pOut, fOut, aOut, bOut,
                                                       dW0, db0, dW1, db1, dW2, db2,
                                                       sig, outMain);
}

// round 5
// speedup vs baseline: 1.9333x; 1.0933x over previous
#include <cuda_runtime.h>
#include <math_constants.h>

#define T_LEN 8192
#define B_SZ  256
#define E_CH  8
#define KS    15
#define TD    1024
#define TPI_F 6.28318530717958647692f

#define PAD(i)   ((i) + ((i) >> 5))
#define F2PAD(i) ((i) + ((i) >> 4))

typedef unsigned long long ull;

// ---- packed f32x2 helpers ----
__device__ __forceinline__ ull pk2(float lo, float hi) {
    ull r;
    asm("mov.b64 %0, {%1, %2};" : "=l"(r) : "f"(lo), "f"(hi));
    return r;
}
__device__ __forceinline__ float2 unpk2(ull v) {
    float lo, hi;
    asm("mov.b64 {%0, %1}, %2;" : "=f"(lo), "=f"(hi) : "l"(v));
    return make_float2(lo, hi);
}
__device__ __forceinline__ ull fma2(ull a, ull b, ull c) {
    ull d;
    asm("fma.rn.f32x2 %0, %1, %2, %3;" : "=l"(d) : "l"(a), "l"(b), "l"(c));
    return d;
}
__device__ __forceinline__ ull add2(ull a, ull b) {
    ull d;
    asm("add.rn.f32x2 %0, %1, %2;" : "=l"(d) : "l"(a), "l"(b));
    return d;
}

__device__ __forceinline__ float2 cmulf(float2 a, float2 b) {
    return make_float2(a.x * b.x - a.y * b.y, a.x * b.y + a.y * b.x);
}
__device__ __forceinline__ float2 cadd(float2 a, float2 b) {
    return make_float2(a.x + b.x, a.y + b.y);
}
__device__ __forceinline__ float2 csub(float2 a, float2 b) {
    return make_float2(a.x - b.x, a.y - b.y);
}

// compensated float-float accumulation (TwoSum based)
__device__ __forceinline__ float2 df_add(float2 a, float2 b) {
    float s = a.x + b.x;
    float v = s - a.x;
    float e = (a.x - (s - v)) + (b.x - v);
    e = e + a.y + b.y;
    float hi = s + e;
    return make_float2(hi, e - (hi - s));
}
__device__ __forceinline__ float2 df_addf(float2 a, float b) {
    return df_add(a, make_float2(b, 0.f));
}

// ---------------------------------------------------------------------------
// Kernel A: fused per-channel dilated conv pair -> latent (B,E,T)
// Coset-blocked register streaming + packed f32x2 math.
// h channels packed in one 64-bit smem word.
// ---------------------------------------------------------------------------
__global__ __launch_bounds__(256, 2) void latent_kernel(
    const float* __restrict__ x,
    const float* __restrict__ W1, const float* __restrict__ b1,
    const float* __restrict__ W2, const float* __restrict__ b2,
    float* __restrict__ latent)
{
    extern __shared__ float sm[];
    float* sx  = sm;                               // PAD(8192) -> 8448 floats
    ull*   shp = (ull*)(sm + 8448);                // F2PAD(8192) -> 8704 ull

    const int be = blockIdx.x;
    const int e  = be & 7;
    const int b  = be >> 3;
    const int d  = 1 << e;
    const int tid = threadIdx.x;

    const float* xrow = x + (size_t)b * T_LEN;
    for (int i = tid; i < T_LEN; i += 256) sx[PAD(i)] = xrow[i];

    ull w1pk[KS];
#pragma unroll
    for (int j = 0; j < KS; j++)
        w1pk[j] = pk2(W1[e * 30 + j], W1[e * 30 + 15 + j]);
    const ull bias1 = pk2(b1[2 * e], b1[2 * e + 1]);
    __syncthreads();

    // ---- stage 1: packed h = (h0,h1)
#pragma unroll 1
    for (int it = 0; it < 4; it++) {
        const int cc = it * 256 + tid;
        const int p  = cc & (d - 1);
        const int qc = cc >> e;
        const int tb = p + (qc << (e + 3));
        ull xd[22];
#pragma unroll
        for (int m = 0; m < 22; m++) {
            int idx = tb + (m - 7) * d;
            float v = ((unsigned)idx < (unsigned)T_LEN) ? sx[PAD(idx)] : 0.f;
            xd[m] = pk2(v, v);
        }
#pragma unroll
        for (int rr = 0; rr < 8; rr++) {
            ull a0 = bias1, a1 = 0ULL;
#pragma unroll
            for (int j = 0; j < KS; j += 2) a0 = fma2(w1pk[j], xd[rr + j], a0);
#pragma unroll
            for (int j = 1; j < KS; j += 2) a1 = fma2(w1pk[j], xd[rr + j], a1);
            shp[F2PAD(tb + rr * d)] = add2(a0, a1);
        }
    }

    ull w2pk[KS];
#pragma unroll
    for (int k = 0; k < KS; k++)
        w2pk[k] = pk2(W2[e * 30 + k], W2[e * 30 + 15 + k]);
    const ull bias2 = pk2(b2[e], 0.f);
    __syncthreads();

    // ---- stage 2: packed dot over (h0,h1), results staged into sx
#pragma unroll 1
    for (int it = 0; it < 4; it++) {
        const int cc = it * 256 + tid;
        const int p  = cc & (d - 1);
        const int qc = cc >> e;
        const int tb = p + (qc << (e + 3));
        ull gp[22];
#pragma unroll
        for (int m = 0; m < 22; m++) {
            int idx = tb + (m - 7) * d;
            gp[m] = ((unsigned)idx < (unsigned)T_LEN) ? shp[F2PAD(idx)] : 0ULL;
        }
#pragma unroll
        for (int rr = 0; rr < 8; rr++) {
            ull a0 = bias2, a1 = 0ULL;
#pragma unroll
            for (int k = 0; k < KS; k += 2) a0 = fma2(w2pk[k], gp[rr + k], a0);
#pragma unroll
            for (int k = 1; k < KS; k += 2) a1 = fma2(w2pk[k], gp[rr + k], a1);
            float2 r = unpk2(add2(a0, a1));
            sx[PAD(tb + rr * d)] = r.x + r.y;
        }
    }
    __syncthreads();

    float* lrow = latent + (size_t)be * T_LEN;
    for (int i = tid; i < T_LEN; i += 256) lrow[i] = sx[PAD(i)];
}

// ---------------------------------------------------------------------------
// Kernel B: per-(b,e) row — fc dots, real FFT (8192 real via complex 4096),
// radix-8 Stockham (4 stages, 512 threads), padded smem,
// compensated fp32 reductions.
// ---------------------------------------------------------------------------
__global__ __launch_bounds__(512, 2) void fft_kernel(
    const float* __restrict__ latent,
    const float* __restrict__ fcW, const float* __restrict__ fcb,
    float* __restrict__ pOut, float* __restrict__ fOut,
    float* __restrict__ aOut, float* __restrict__ bOut)
{
    const int M = 4096;
    extern __shared__ float smf[];
    float2* bufA = (float2*)smf;         // F2PAD -> 4352 slots
    float2* bufB = bufA + 4352;
    float2* tw   = bufB + 4352;          // 512 twiddles
    __shared__ float2 red2[64];

    const int be = blockIdx.x;
    const int e  = be & 7;
    const int tid = threadIdx.x;

    const float2* rowc = (const float2*)(latent + (size_t)be * T_LEN);
    const float2* fw0  = (const float2*)(fcW + (size_t)(e * 2 + 0) * T_LEN);
    const float2* fw1  = (const float2*)(fcW + (size_t)(e * 2 + 1) * T_LEN);

    float2 v0 = make_float2(0.f, 0.f), v1 = make_float2(0.f, 0.f);
#pragma unroll
    for (int i = tid; i < M; i += 512) {
        float2 z = rowc[i];
        bufA[F2PAD(i)] = z;
        float2 a0 = fw0[i], a1 = fw1[i];
        v0 = df_addf(v0, z.x * a0.x + z.y * a0.y);
        v1 = df_addf(v1, z.x * a1.x + z.y * a1.y);
    }
    {
        float s, c;
        sincosf(-(float)CUDART_PI * (float)tid / 2048.0f, &s, &c);
        tw[tid] = make_float2(c, s);
    }
    __syncthreads();

    // radix-8 Stockham autosort, 4 stages, M = 8^4
    const float RS = 0.70710678118654752440f;
    float2* bin  = bufA;
    float2* bout = bufB;
#pragma unroll
    for (int sg = 0; sg < 4; sg++) {
        const int m = 1 << (3 * sg);
        const int idx = tid;
        const int r = idx & (m - 1);
        float2 W = tw[r << (9 - 3 * sg)];

        float2 u0 = bin[F2PAD(idx)];
        float2 z1 = bin[F2PAD(idx + 512)];
        float2 z2 = bin[F2PAD(idx + 1024)];
        float2 z3 = bin[F2PAD(idx + 1536)];
        float2 z4 = bin[F2PAD(idx + 2048)];
        float2 z5 = bin[F2PAD(idx + 2560)];
        float2 z6 = bin[F2PAD(idx + 3072)];
        float2 z7 = bin[F2PAD(idx + 3584)];

        float2 Wc = W;
        float2 u1 = cmulf(z1, Wc); Wc = cmulf(Wc, W);
        float2 u2 = cmulf(z2, Wc); Wc = cmulf(Wc, W);
        float2 u3 = cmulf(z3, Wc); Wc = cmulf(Wc, W);
        float2 u4 = cmulf(z4, Wc); Wc = cmulf(Wc, W);
        float2 u5 = cmulf(z5, Wc); Wc = cmulf(Wc, W);
        float2 u6 = cmulf(z6, Wc); Wc = cmulf(Wc, W);
        float2 u7 = cmulf(z7, Wc);

        float2 t0 = cadd(u0, u4), t1 = csub(u0, u4);
        float2 t2 = cadd(u2, u6), t3 = csub(u2, u6);
        float2 E0 = cadd(t0, t2);
        float2 E1 = make_float2(t1.x + t3.y, t1.y - t3.x);
        float2 E2 = csub(t0, t2);
        float2 E3 = make_float2(t1.x - t3.y, t1.y + t3.x);
        float2 s0 = cadd(u1, u5), s1 = csub(u1, u5);
        float2 s2 = cadd(u3, u7), s3 = csub(u3, u7);
        float2 O0 = cadd(s0, s2);
        float2 O1 = make_float2(s1.x + s3.y, s1.y - s3.x);
        float2 O2 = csub(s0, s2);
        float2 O3 = make_float2(s1.x - s3.y, s1.y + s3.x);
        float2 Q1 = make_float2(RS * (O1.x + O1.y), RS * (O1.y - O1.x));
        float2 Q2 = make_float2(O2.y, -O2.x);
        float2 Q3 = make_float2(RS * (O3.y - O3.x), -RS * (O3.x + O3.y));

        const int ob = ((idx - r) << 3) + r;
        bout[F2PAD(ob)]         = cadd(E0, O0);
        bout[F2PAD(ob + m)]     = cadd(E1, Q1);
        bout[F2PAD(ob + 2 * m)] = cadd(E2, Q2);
        bout[F2PAD(ob + 3 * m)] = cadd(E3, Q3);
        bout[F2PAD(ob + 4 * m)] = csub(E0, O0);
        bout[F2PAD(ob + 5 * m)] = csub(E1, Q1);
        bout[F2PAD(ob + 6 * m)] = csub(E2, Q2);
        bout[F2PAD(ob + 7 * m)] = csub(E3, Q3);
        __syncthreads();
        float2* tmp = bin; bin = bout; bout = tmp;
    }

    float2 psum = make_float2(0.f, 0.f), wsum = make_float2(0.f, 0.f);
#pragma unroll
    for (int k0 = 0; k0 < 8; k0++) {
        int k = tid + 1 + k0 * 512;
        if (k < M) {
            float2 zk = bin[F2PAD(k)];
            float2 zm = bin[F2PAD(M - k)];
            float Ax = 0.5f * (zk.x + zm.x), Ay = 0.5f * (zk.y - zm.y);
            float Bx = 0.5f * (zk.x - zm.x), By = 0.5f * (zk.y + zm.y);
            float s, c;
            __sincosf(-(float)CUDART_PI * (float)k / (float)M, &s, &c);
            float Xr = Ax + c * By + s * Bx;
            float Xi = Ay - c * Bx + s * By;
            float pw = Xr * Xr + Xi * Xi;
            psum = df_addf(psum, pw);
            wsum = df_addf(wsum, (float)k * pw);
        }
    }
    if (tid == 0) {
        float xm = bin[0].x - bin[0].y;
        psum = df_addf(psum, xm * xm);
        wsum = df_addf(wsum, (float)M * (xm * xm));
    }

    const unsigned mask = 0xffffffffu;
#pragma unroll
    for (int o = 16; o > 0; o >>= 1) {
        psum = df_add(psum, make_float2(__shfl_down_sync(mask, psum.x, o),
                                        __shfl_down_sync(mask, psum.y, o)));
        wsum = df_add(wsum, make_float2(__shfl_down_sync(mask, wsum.x, o),
                                        __shfl_down_sync(mask, wsum.y, o)));
        v0   = df_add(v0,   make_float2(__shfl_down_sync(mask, v0.x, o),
                                        __shfl_down_sync(mask, v0.y, o)));
        v1   = df_add(v1,   make_float2(__shfl_down_sync(mask, v1.x, o),
                                        __shfl_down_sync(mask, v1.y, o)));
    }
    const int warp = tid >> 5, lane = tid & 31;
    if (lane == 0) {
        red2[warp] = psum; red2[16 + warp] = wsum;
        red2[32 + warp] = v0; red2[48 + warp] = v1;
    }
    __syncthreads();
    if (tid == 0) {
        double P = 0, Wm = 0, V0 = 0, V1 = 0;
        for (int i = 0; i < 16; i++) {
            P  += (double)red2[i].x      + (double)red2[i].y;
            Wm += (double)red2[16 + i].x + (double)red2[16 + i].y;
            V0 += (double)red2[32 + i].x + (double)red2[32 + i].y;
            V1 += (double)red2[48 + i].x + (double)red2[48 + i].y;
        }
        V0 += (double)fcb[e * 2];
        V1 += (double)fcb[e * 2 + 1];
        float f    = (float)(0.5 * Wm / P);
        float a    = 2.0f * sqrtf((float)P) / (float)T_LEN;
        float boff = (bin[0].x + bin[0].y) / (float)T_LEN;
        float p    = atan2f((float)V1, (float)V0) / TPI_F;
        pOut[be] = p; fOut[be] = f; aOut[be] = a; bOut[be] = boff;
    }
}

// ---------------------------------------------------------------------------
// Kernel D: sinusoid resynthesis via rotation recurrence + fused 3-level
// grouped deconv tree with packed f32x2 dots.
// ---------------------------------------------------------------------------
__global__ __launch_bounds__(256) void sig_tree_kernel(
    const float* __restrict__ pArr, const float* __restrict__ fArr,
    const float* __restrict__ aArr, const float* __restrict__ bArr,
    const float* __restrict__ dW0, const float* __restrict__ db0,
    const float* __restrict__ dW1, const float* __restrict__ db1,
    const float* __restrict__ dW2, const float* __restrict__ db2,
    float* __restrict__ sig, float* __restrict__ outp)
{
    extern __shared__ float smd[];
    const int SW  = TD + 42;
    const int W0L = TD + 28;
    const int W1L = TD + 14;
    float2* ssig2 = (float2*)smd;
    float2* sy0_2 = ssig2 + 4 * SW;
    float2* sy1_2 = sy0_2 + 2 * W0L;
    __shared__ float sca[8], scf[8], scp[8], scb[8];
    __shared__ float2 rotv[8];
    __shared__ ull sdw0p[4 * KS], sdw1p[2 * KS], sdw2p[KS];
    __shared__ float sdb0[4], sdb1[2], sdb2[1];

    const int blk  = blockIdx.x;
    const int tile = blk & 7;
    const int b    = blk >> 3;
    const int t0   = tile * TD;
    const int tid  = threadIdx.x;
    const float inv = 2.0f / (float)(T_LEN - 1);

    if (tid < 8) {
        float fv = fArr[b * 8 + tid];
        sca[tid] = aArr[b * 8 + tid]; scf[tid] = fv;
        scp[tid] = pArr[b * 8 + tid]; scb[tid] = bArr[b * 8 + tid];
        float S, C;
        sincospif(2.0f * fv * inv, &S, &C);
        rotv[tid] = make_float2(C, S);
    }
    if (tid < 4 * KS) {
        int g = tid / KS, k = tid - g * KS;
        sdw0p[tid] = pk2(dW0[(2 * g) * KS + k], dW0[(2 * g + 1) * KS + k]);
    }
    if (tid < 2 * KS) {
        int g = tid / KS, k = tid - g * KS;
        sdw1p[tid] = pk2(dW1[(2 * g) * KS + k], dW1[(2 * g + 1) * KS + k]);
    }
    if (tid < KS) sdw2p[tid] = pk2(dW2[tid], dW2[KS + tid]);
    if (tid < 4) sdb0[tid] = db0[tid];
    if (tid < 2) sdb1[tid] = db1[tid];
    if (tid == 0) sdb2[0] = db2[0];
    __syncthreads();

    // sinusoid generation: 64 threads per pair-row, 17 contiguous elems each
    {
        const int pr  = tid >> 6;
        const int sub = tid & 63;
        const int j0  = sub * 17;
        const int ts  = t0 - 21 + j0;
        const int e0 = 2 * pr, e1 = 2 * pr + 1;
        const float arg0 = -1.0f + (float)ts * inv;
        float s0, c0, s1, c1;
        sincospif(2.0f * (scf[e0] * arg0 + scp[e0]), &s0, &c0);
        sincospif(2.0f * (scf[e1] * arg0 + scp[e1]), &s1, &c1);
        const float2 r0 = rotv[e0], r1 = rotv[e1];
        const float a0 = sca[e0], b0 = scb[e0];
        const float a1 = sca[e1], b1v = scb[e1];
#pragma unroll
        for (int jj = 0; jj < 17; jj++) {
            int j = j0 + jj;
            int t = ts + jj;
            if (j < SW) {
                bool ok = ((unsigned)t < (unsigned)T_LEN);
                float v0 = ok ? (a0 * s0 + b0)  : 0.f;
                float v1 = ok ? (a1 * s1 + b1v) : 0.f;
                ssig2[pr * SW + j] = make_float2(v0, v1);
            }
            float ns0 = s0 * r0.x + c0 * r0.y;
            c0 = c0 * r0.x - s0 * r0.y; s0 = ns0;
            float ns1 = s1 * r1.x + c1 * r1.y;
            c1 = c1 * r1.x - s1 * r1.y; s1 = ns1;
        }
    }
    __syncthreads();

    // coalesced sig writeback
    for (int i = tid; i < 8 * TD; i += 256) {
        int e = i >> 10, jj = i & (TD - 1);
        float2 v = ssig2[(e >> 1) * SW + 21 + jj];
        sig[((size_t)b * 8 + e) * T_LEN + t0 + jj] = (e & 1) ? v.y : v.x;
    }

    // level 0: 4 groups, packed dots
#pragma unroll 1
    for (int g = 0; g < 4; g++) {
        const ull* srow = (const ull*)(ssig2 + g * SW);
        ull wp[KS];
#pragma unroll
        for (int k = 0; k < KS; k++) wp[k] = sdw0p[g * KS + k];
        const ull bg = pk2(sdb0[g], 0.f);
        float* dst = (float*)(sy0_2 + (g >> 1) * W0L);
        const int comp = g & 1;
        for (int j = tid; j < W0L; j += 256) {
            int t = t0 - 14 + j;
            float acc = 0.f;
            if ((unsigned)t < (unsigned)T_LEN) {
                const ull* s = srow + j;
                ull a0 = bg, a1 = 0ULL;
#pragma unroll
                for (int k = 0; k < KS; k += 2) a0 = fma2(wp[k], s[k], a0);
#pragma unroll
                for (int k = 1; k < KS; k += 2) a1 = fma2(wp[k], s[k], a1);
                float2 r = unpk2(add2(a0, a1));
                acc = r.x + r.y;
            }
            dst[2 * j + comp] = acc;
        }
    }
    __syncthreads();

    // level 1: 2 groups
#pragma unroll 1
    for (int g = 0; g < 2; g++) {
        const ull* srow = (const ull*)(sy0_2 + g * W0L);
        ull wp[KS];
#pragma unroll
        for (int k = 0; k < KS; k++) wp[k] = sdw1p[g * KS + k];
        const ull bg = pk2(sdb1[g], 0.f);
        float* dst = (float*)sy1_2;
        for (int j = tid; j < W1L; j += 256) {
            int t = t0 - 7 + j;
            float acc = 0.f;
            if ((unsigned)t < (unsigned)T_LEN) {
                const ull* s = srow + j;
                ull a0 = bg, a1 = 0ULL;
#pragma unroll
                for (int k = 0; k < KS; k += 2) a0 = fma2(wp[k], s[k], a0);
#pragma unroll
                for (int k = 1; k < KS; k += 2) a1 = fma2(wp[k], s[k], a1);
                float2 r = unpk2(add2(a0, a1));
                acc = r.x + r.y;
            }
            dst[2 * j + g] = acc;
        }
    }
    __syncthreads();

    // level 2
    {
        ull wp[KS];
#pragma unroll
        for (int k = 0; k < KS; k++) wp[k] = sdw2p[k];
        const ull bg = pk2(sdb2[0], 0.f);
        for (int j = tid; j < TD; j += 256) {
            const ull* s = (const ull*)sy1_2 + j;
            ull a0 = bg, a1 = 0ULL;
#pragma unroll
            for (int k = 0; k < KS; k += 2) a0 = fma2(wp[k], s[k], a0);
#pragma unroll
            for (int k = 1; k < KS; k += 2) a1 = fma2(wp[k], s[k], a1);
            float2 r = unpk2(add2(a0, a1));
            outp[(size_t)b * T_LEN + t0 + j] = r.x + r.y;
        }
    }
}

// ---------------------------------------------------------------------------
extern "C" void kernel_launch(void* const* d_in, const int* in_sizes, int n_in,
                              void* d_out, int out_size)
{
    const float* x   = (const float*)d_in[0];
    const float* W1  = (const float*)d_in[1];
    const float* b1  = (const float*)d_in[2];
    const float* W2  = (const float*)d_in[3];
    const float* b2  = (const float*)d_in[4];
    const float* fcW = (const float*)d_in[5];
    const float* fcb = (const float*)d_in[6];
    const float* dW0 = (const float*)d_in[7];
    const float* db0 = (const float*)d_in[8];
    const float* dW1 = (const float*)d_in[9];
    const float* db1 = (const float*)d_in[10];
    const float* dW2 = (const float*)d_in[11];
    const float* db2 = (const float*)d_in[12];

    float* out = (float*)d_out;
    float* outMain = out;                                        // (B, T)
    float* latent  = out + (size_t)B_SZ * T_LEN;                 // (B, E, T)
    float* sig     = latent + (size_t)B_SZ * E_CH * T_LEN;       // (B, E, T)
    float* pOut    = sig + (size_t)B_SZ * E_CH * T_LEN;          // (B, E, 1)
    float* fOut    = pOut + B_SZ * E_CH;
    float* aOut    = fOut + B_SZ * E_CH;
    float* bOut    = aOut + B_SZ * E_CH;

    const size_t smA = (size_t)8448 * sizeof(float) + (size_t)8704 * sizeof(ull);
    const size_t smB = (size_t)(4352 * 2 + 512) * sizeof(float2);
    const size_t smD = (size_t)(4 * (TD + 42) + 2 * (TD + 28) + (TD + 14)) * sizeof(float2);

    cudaFuncSetAttribute(latent_kernel,   cudaFuncAttributeMaxDynamicSharedMemorySize, (int)smA);
    cudaFuncSetAttribute(fft_kernel,      cudaFuncAttributeMaxDynamicSharedMemorySize, (int)smB);
    cudaFuncSetAttribute(sig_tree_kernel, cudaFuncAttributeMaxDynamicSharedMemorySize, (int)smD);

    latent_kernel<<<B_SZ * E_CH, 256, smA>>>(x, W1, b1, W2, b2, latent);
    fft_kernel<<<B_SZ * E_CH, 512, smB>>>(latent, fcW, fcb, pOut, fOut, aOut, bOut);
    sig_tree_kernel<<<B_SZ * (T_LEN / TD), 256, smD>>>(pOut, fOut, aOut, bOut,
                                                       dW0, db0, dW1, db1, dW2, db2,
                                                       sig, outMain);
}